// round 2
// baseline (speedup 1.0000x reference)
#include <cuda_runtime.h>
#include <cuda_bf16.h>
#include <math.h>

// ---------------------------------------------------------------------------
// Problem: HybridQCNNQLSTM
//   B=256, S=1024, H=256
//   Stage 1: per-element MLP 1->16->16->12->8->4->4 (tanh) -> 1 (linear)
//   Stage 2: LSTM over S=1024 steps, hidden 256, input dim 1
//   Outputs: cnn_features (B*S floats) then logits (B floats)
// ---------------------------------------------------------------------------

#define BATCH 256
#define SEQ   1024
#define HID   256

// ======================= Stage 1: CNN MLP kernel ===========================

template<int DIN, int DOUT>
__device__ __forceinline__ void layer_tanh(const float* __restrict__ w,
                                           const float* __restrict__ b,
                                           const float* in, float* out) {
#pragma unroll
    for (int o = 0; o < DOUT; ++o) {
        float s = b[o];
#pragma unroll
        for (int i = 0; i < DIN; ++i) s = fmaf(w[o * DIN + i], in[i], s);
        out[o] = tanhf(s);
    }
}

__global__ void __launch_bounds__(256) cnn_kernel(
    const float* __restrict__ x,
    const float* __restrict__ w1, const float* __restrict__ b1,
    const float* __restrict__ w2, const float* __restrict__ b2,
    const float* __restrict__ w3, const float* __restrict__ b3,
    const float* __restrict__ w4, const float* __restrict__ b4,
    const float* __restrict__ w5, const float* __restrict__ b5,
    const float* __restrict__ w6, const float* __restrict__ b6,
    const float* __restrict__ w7, const float* __restrict__ b7,
    float* __restrict__ out)
{
    __shared__ float ws[673];
    const int tid = threadIdx.x;

    // Copy all small weights/biases into shared memory (broadcast reads later).
    {
        const float* srcs[14] = {w1,b1,w2,b2,w3,b3,w4,b4,w5,b5,w6,b6,w7,b7};
        const int    lens[14] = {16,16,256,16,192,12,96,8,32,4,16,4,4,1};
        int off = 0;
        for (int s = 0; s < 14; ++s) {
            for (int i = tid; i < lens[s]; i += 256) ws[off + i] = srcs[s][i];
            off += lens[s];
        }
    }
    __syncthreads();

    const int e = blockIdx.x * 256 + tid;   // grid sized exactly B*S/256
    float v = x[e];
    float h1[16], h2[16], h3[12], h4[8], h5[4], h6[4];
    layer_tanh<1, 16>(ws + 0,   ws + 16,  &v, h1);
    layer_tanh<16,16>(ws + 32,  ws + 288, h1, h2);
    layer_tanh<16,12>(ws + 304, ws + 496, h2, h3);
    layer_tanh<12, 8>(ws + 508, ws + 604, h3, h4);
    layer_tanh<8,  4>(ws + 612, ws + 644, h4, h5);
    layer_tanh<4,  4>(ws + 648, ws + 664, h5, h6);
    float o = ws[672];   // b7
#pragma unroll
    for (int i = 0; i < 4; ++i) o = fmaf(ws[668 + i], h6[i], o);
    out[e] = o;
}

// ======================= Stage 2: LSTM kernel ==============================
//
// Grid: 128 CTAs = 16 clusters of 8 CTAs.
//   cluster (group) g handles batches [16g, 16g+16)
//   CTA rank r in cluster handles hidden units [32r, 32r+32) (all 4 gates)
// Weights for this CTA's hidden slice live in shared memory for the entire
// kernel: w_sm[k][h_local][gate] (k = source hidden index), 128 KB.
// hx is exchanged via a double-buffered __device__ global, layout per group
// [h(256)][b(16)], using .cg loads/stores (L2-coherent) and cluster barriers.
// cx lives in thread registers for the whole sequence.

#define CLUSTER_CTAS  8
#define GROUP_B       16
#define H_PER_CTA     32
#define LSTM_THREADS  256

// smem float offsets
#define W_SM_OFF   0                       // [256][32][4]  = 32768
#define HX_SM_OFF  32768                   // [256][16]     = 4096
#define XS_OFF     36864                   // [16]
#define WX_OFF     36880                   // [32][4]
#define BIAS_OFF   37008                   // [32][4]
#define SMEM_FLOATS 37136
#define SMEM_BYTES (SMEM_FLOATS * 4)

__device__ float g_hx[2 * BATCH * HID];    // [buf][group][h:256][b:16]

__device__ __forceinline__ float sigmoidf(float v) {
    return 1.0f / (1.0f + expf(-v));
}

#define CLUSTER_SYNC_() do { \
    asm volatile("barrier.cluster.arrive.aligned;" ::: "memory"); \
    asm volatile("barrier.cluster.wait.aligned;"   ::: "memory"); \
} while (0)

__global__ void __launch_bounds__(LSTM_THREADS, 1) __cluster_dims__(CLUSTER_CTAS, 1, 1)
lstm_kernel(const float* __restrict__ xfeat,     // [B][S] cnn features
            const float* __restrict__ w_f, const float* __restrict__ b_f,
            const float* __restrict__ w_i, const float* __restrict__ b_i,
            const float* __restrict__ w_g, const float* __restrict__ b_g,
            const float* __restrict__ w_o, const float* __restrict__ b_o,
            const float* __restrict__ w_head, const float* __restrict__ b_head,
            float* __restrict__ logits)
{
    extern __shared__ float sm[];
    float* w_sm   = sm + W_SM_OFF;
    float* hx_sm  = sm + HX_SM_OFF;
    float* xs     = sm + XS_OFF;
    float* wx_sm  = sm + WX_OFF;
    float* bias_sm= sm + BIAS_OFF;

    const int tid     = threadIdx.x;
    const int ctarank = blockIdx.x & (CLUSTER_CTAS - 1);
    const int group   = blockIdx.x >> 3;
    const int h0      = ctarank * H_PER_CTA;
    const int b0      = group * GROUP_B;

    {
        const float* Wg[4] = {w_f, w_i, w_g, w_o};
        const float* Bg[4] = {b_f, b_i, b_g, b_o};
        // w_sm[k*128 + h*4 + g] = Wg[g][(h0+h)*257 + 1 + k]
        for (int idx = tid; idx < 256 * H_PER_CTA * 4; idx += LSTM_THREADS) {
            int k = idx >> 7;
            int r = idx & 127;
            int h = r >> 2;
            int g = r & 3;
            w_sm[idx] = Wg[g][(h0 + h) * 257 + 1 + k];
        }
        if (tid < 128) {
            int h = tid >> 2, g = tid & 3;
            wx_sm[tid]   = Wg[g][(h0 + h) * 257];
            bias_sm[tid] = Bg[g][h0 + h];
        }
    }

    // zero our slice of hx buffer 0: [0][group][h0..h0+31][0..15]
    for (int idx = tid; idx < H_PER_CTA * GROUP_B; idx += LSTM_THREADS) {
        g_hx[group * (HID * GROUP_B) + (h0 + (idx >> 4)) * GROUP_B + (idx & 15)] = 0.0f;
    }
    __threadfence();
    CLUSTER_SYNC_();

    const int h_local = tid & 31;       // hidden within slice (lane id)
    const int b_pair  = tid >> 5;       // warp id -> batch pair (2 batches)
    float cx0 = 0.0f, cx1 = 0.0f;
    int p = 0;

    const float* wp = w_sm + h_local * 4;
    const float* hp = hx_sm + b_pair * 2;

    for (int t = 0; t < SEQ; ++t) {
        // load full hx (256 x 16) for this group into shared [k][b]
        const float* src = g_hx + p * (BATCH * HID) + group * (HID * GROUP_B);
#pragma unroll
        for (int j = 0; j < 4; ++j) {
            int idx = j * 1024 + tid * 4;
            float4 v = __ldcg((const float4*)(src + idx));
            *(float4*)(hx_sm + idx) = v;
        }
        if (tid < GROUP_B) xs[tid] = __ldg(xfeat + (b0 + tid) * SEQ + t);
        __syncthreads();

        const float xa = xs[b_pair * 2 + 0];
        const float xb = xs[b_pair * 2 + 1];
        float af0 = fmaf(wx_sm[h_local*4+0], xa, bias_sm[h_local*4+0]);
        float af1 = fmaf(wx_sm[h_local*4+0], xb, bias_sm[h_local*4+0]);
        float ai0 = fmaf(wx_sm[h_local*4+1], xa, bias_sm[h_local*4+1]);
        float ai1 = fmaf(wx_sm[h_local*4+1], xb, bias_sm[h_local*4+1]);
        float ag0 = fmaf(wx_sm[h_local*4+2], xa, bias_sm[h_local*4+2]);
        float ag1 = fmaf(wx_sm[h_local*4+2], xb, bias_sm[h_local*4+2]);
        float ao0 = fmaf(wx_sm[h_local*4+3], xa, bias_sm[h_local*4+3]);
        float ao1 = fmaf(wx_sm[h_local*4+3], xb, bias_sm[h_local*4+3]);

#pragma unroll 8
        for (int k = 0; k < HID; ++k) {
            float4 w4 = *(const float4*)(wp + k * 128);   // f,i,g,o weights at (k, h)
            float2 h2 = *(const float2*)(hp + k * 16);    // hx[k][2 batches] (broadcast)
            af0 = fmaf(w4.x, h2.x, af0); af1 = fmaf(w4.x, h2.y, af1);
            ai0 = fmaf(w4.y, h2.x, ai0); ai1 = fmaf(w4.y, h2.y, ai1);
            ag0 = fmaf(w4.z, h2.x, ag0); ag1 = fmaf(w4.z, h2.y, ag1);
            ao0 = fmaf(w4.w, h2.x, ao0); ao1 = fmaf(w4.w, h2.y, ao1);
        }

        float f0 = sigmoidf(af0), i0 = sigmoidf(ai0), gg0 = tanhf(ag0), o0 = sigmoidf(ao0);
        float f1 = sigmoidf(af1), i1 = sigmoidf(ai1), gg1 = tanhf(ag1), o1 = sigmoidf(ao1);
        cx0 = fmaf(f0, cx0, i0 * gg0);
        cx1 = fmaf(f1, cx1, i1 * gg1);
        float hx0 = o0 * tanhf(cx0);
        float hx1 = o1 * tanhf(cx1);

        float* dst = g_hx + (p ^ 1) * (BATCH * HID) + group * (HID * GROUP_B)
                   + (h0 + h_local) * GROUP_B + b_pair * 2;
        __stcg((float2*)dst, make_float2(hx0, hx1));
        __threadfence();
        CLUSTER_SYNC_();
        p ^= 1;
    }

    // Head: logits[b] = hx_final[b] . w_head + b_head, computed by rank-0 CTA.
    if (ctarank == 0) {
        const float* src = g_hx + p * (BATCH * HID) + group * (HID * GROUP_B);
        const int b_l  = tid >> 4;   // 0..15
        const int part = tid & 15;   // 0..15
        float s = 0.0f;
#pragma unroll
        for (int kk = 0; kk < 16; ++kk) {
            int h = part * 16 + kk;
            s = fmaf(__ldcg(src + h * GROUP_B + b_l), __ldg(w_head + h), s);
        }
        s += __shfl_xor_sync(0xffffffffu, s, 8);
        s += __shfl_xor_sync(0xffffffffu, s, 4);
        s += __shfl_xor_sync(0xffffffffu, s, 2);
        s += __shfl_xor_sync(0xffffffffu, s, 1);
        if (part == 0) logits[b0 + b_l] = s + __ldg(b_head);
    }
}

// ======================= launch ===========================================

extern "C" void kernel_launch(void* const* d_in, const int* in_sizes, int n_in,
                              void* d_out, int out_size)
{
    const float* x      = (const float*)d_in[0];
    const float* w1     = (const float*)d_in[1];
    const float* b1     = (const float*)d_in[2];
    const float* w2     = (const float*)d_in[3];
    const float* b2     = (const float*)d_in[4];
    const float* w3     = (const float*)d_in[5];
    const float* b3     = (const float*)d_in[6];
    const float* w4     = (const float*)d_in[7];
    const float* b4     = (const float*)d_in[8];
    const float* w5     = (const float*)d_in[9];
    const float* b5     = (const float*)d_in[10];
    const float* w6     = (const float*)d_in[11];
    const float* b6     = (const float*)d_in[12];
    const float* w7     = (const float*)d_in[13];
    const float* b7     = (const float*)d_in[14];
    const float* w_f    = (const float*)d_in[15];
    const float* b_f    = (const float*)d_in[16];
    const float* w_i    = (const float*)d_in[17];
    const float* b_i    = (const float*)d_in[18];
    const float* w_g    = (const float*)d_in[19];
    const float* b_g    = (const float*)d_in[20];
    const float* w_o    = (const float*)d_in[21];
    const float* b_o    = (const float*)d_in[22];
    const float* w_head = (const float*)d_in[23];
    const float* b_head = (const float*)d_in[24];

    float* out = (float*)d_out;

    // Stage 1: cnn_features -> out[0 .. B*S)
    cnn_kernel<<<(BATCH * SEQ) / 256, 256>>>(x, w1, b1, w2, b2, w3, b3, w4, b4,
                                             w5, b5, w6, b6, w7, b7, out);

    // Stage 2: LSTM, logits -> out[B*S .. B*S + B)
    cudaFuncSetAttribute(lstm_kernel, cudaFuncAttributeMaxDynamicSharedMemorySize,
                         SMEM_BYTES);
    lstm_kernel<<<128, LSTM_THREADS, SMEM_BYTES>>>(
        out, w_f, b_f, w_i, b_i, w_g, b_g, w_o, b_o, w_head, b_head,
        out + BATCH * SEQ);
}

// round 3
// speedup vs baseline: 1.1834x; 1.1834x over previous
#include <cuda_runtime.h>
#include <cuda_bf16.h>
#include <math.h>

// ---------------------------------------------------------------------------
// HybridQCNNQLSTM : B=256, S=1024, H=256
//   Stage 1: per-element MLP 1->16->16->12->8->4->4 (tanh) -> 1 (linear)
//   Stage 2: LSTM over S=1024 steps, hidden 256, input dim 1
//   out = [cnn_features (B*S) | logits (B)]
// ---------------------------------------------------------------------------

#define BATCH 256
#define SEQ   1024
#define HID   256

// ======================= Stage 1: CNN MLP kernel ===========================

template<int DIN, int DOUT>
__device__ __forceinline__ void layer_tanh(const float* __restrict__ w,
                                           const float* __restrict__ b,
                                           const float* in, float* out) {
#pragma unroll
    for (int o = 0; o < DOUT; ++o) {
        float s = b[o];
#pragma unroll
        for (int i = 0; i < DIN; ++i) s = fmaf(w[o * DIN + i], in[i], s);
        out[o] = tanhf(s);
    }
}

__global__ void __launch_bounds__(256) cnn_kernel(
    const float* __restrict__ x,
    const float* __restrict__ w1, const float* __restrict__ b1,
    const float* __restrict__ w2, const float* __restrict__ b2,
    const float* __restrict__ w3, const float* __restrict__ b3,
    const float* __restrict__ w4, const float* __restrict__ b4,
    const float* __restrict__ w5, const float* __restrict__ b5,
    const float* __restrict__ w6, const float* __restrict__ b6,
    const float* __restrict__ w7, const float* __restrict__ b7,
    float* __restrict__ out)
{
    __shared__ float ws[673];
    const int tid = threadIdx.x;
    {
        const float* srcs[14] = {w1,b1,w2,b2,w3,b3,w4,b4,w5,b5,w6,b6,w7,b7};
        const int    lens[14] = {16,16,256,16,192,12,96,8,32,4,16,4,4,1};
        int off = 0;
        for (int s = 0; s < 14; ++s) {
            for (int i = tid; i < lens[s]; i += 256) ws[off + i] = srcs[s][i];
            off += lens[s];
        }
    }
    __syncthreads();

    const int e = blockIdx.x * 256 + tid;
    float v = x[e];
    float h1[16], h2[16], h3[12], h4[8], h5[4], h6[4];
    layer_tanh<1, 16>(ws + 0,   ws + 16,  &v, h1);
    layer_tanh<16,16>(ws + 32,  ws + 288, h1, h2);
    layer_tanh<16,12>(ws + 304, ws + 496, h2, h3);
    layer_tanh<12, 8>(ws + 508, ws + 604, h3, h4);
    layer_tanh<8,  4>(ws + 612, ws + 644, h4, h5);
    layer_tanh<4,  4>(ws + 648, ws + 664, h5, h6);
    float o = ws[672];
#pragma unroll
    for (int i = 0; i < 4; ++i) o = fmaf(ws[668 + i], h6[i], o);
    out[e] = o;
}

// ======================= Stage 2: LSTM kernel ==============================
//
// 16 clusters x 8 CTAs. Cluster g: batches [16g,16g+16). CTA rank r: hidden
// [32r,32r+32), all 4 gates, weights smem-resident ([k][h][gate] float4 rows).
//
// Thread layout (256 threads, 8 warps):
//   warp w: bq = w & 3 (batch quad), kh = w >> 2 (K half)
//   lane   = h_local (0..31)
//   thread accumulates 4 gates x 4 batches over 128 k -> 16 indep accumulators
// Cross-K reduction through smem; warps kh==0 own cx and the epilogue.
// hx exchanged through double-buffered __device__ global via .cg + cluster bar.

#define CLUSTER_CTAS  8
#define GROUP_B       16
#define H_PER_CTA     32
#define LSTM_THREADS  256

// smem float offsets
#define W_SM_OFF    0                      // [256 k][32 h][4 g]   = 32768
#define HX_SM_OFF   32768                  // [256 k][16 b]        = 4096
#define RED_OFF     36864                  // [16][128]            = 2048
#define XS_OFF      38912                  // [16]
#define WX4_OFF     38928                  // [32] float4          = 128
#define B4_OFF      39056                  // [32] float4          = 128
#define SMEM_FLOATS 39184
#define SMEM_BYTES  (SMEM_FLOATS * 4)

__device__ float g_hx[2 * BATCH * HID];    // [buf][group][h:256][b:16]

__device__ __forceinline__ float fast_sigmoid(float v) {
    return __fdividef(1.0f, 1.0f + __expf(-v));
}
__device__ __forceinline__ float fast_tanh(float v) {
    // tanh(x) = 1 - 2/(exp(2x)+1); __expf rel err ~2^-21
    return 1.0f - __fdividef(2.0f, __expf(2.0f * v) + 1.0f);
}

#define CLUSTER_SYNC_() do { \
    asm volatile("barrier.cluster.arrive.aligned;" ::: "memory"); \
    asm volatile("barrier.cluster.wait.aligned;"   ::: "memory"); \
} while (0)

__global__ void __launch_bounds__(LSTM_THREADS, 1) __cluster_dims__(CLUSTER_CTAS, 1, 1)
lstm_kernel(const float* __restrict__ xfeat,     // [B][S] cnn features
            const float* __restrict__ w_f, const float* __restrict__ b_f,
            const float* __restrict__ w_i, const float* __restrict__ b_i,
            const float* __restrict__ w_g, const float* __restrict__ b_g,
            const float* __restrict__ w_o, const float* __restrict__ b_o,
            const float* __restrict__ w_head, const float* __restrict__ b_head,
            float* __restrict__ logits)
{
    extern __shared__ float sm[];
    float*  w_sm   = sm + W_SM_OFF;
    float*  hx_sm  = sm + HX_SM_OFF;
    float*  red_sm = sm + RED_OFF;
    float*  xs     = sm + XS_OFF;
    float4* wx4_sm = (float4*)(sm + WX4_OFF);
    float4* b4_sm  = (float4*)(sm + B4_OFF);

    const int tid     = threadIdx.x;
    const int ctarank = blockIdx.x & (CLUSTER_CTAS - 1);
    const int group   = blockIdx.x >> 3;
    const int h0      = ctarank * H_PER_CTA;
    const int b0      = group * GROUP_B;

    // ---- load weights into smem: w_sm[k*128 + h*4 + g] = Wg[g][(h0+h)*257+1+k]
    {
        const float* Wg[4] = {w_f, w_i, w_g, w_o};
        const float* Bg[4] = {b_f, b_i, b_g, b_o};
        for (int idx = tid; idx < 256 * H_PER_CTA * 4; idx += LSTM_THREADS) {
            int k = idx >> 7;
            int r = idx & 127;
            int h = r >> 2;
            int g = r & 3;
            w_sm[idx] = Wg[g][(h0 + h) * 257 + 1 + k];
        }
        if (tid < 128) {
            int h = tid >> 2, g = tid & 3;
            ((float*)wx4_sm)[h * 4 + g] = Wg[g][(h0 + h) * 257];
            ((float*)b4_sm)[h * 4 + g]  = Bg[g][h0 + h];
        }
    }

    // zero our slice of hx buffer 0
    for (int idx = tid; idx < H_PER_CTA * GROUP_B; idx += LSTM_THREADS) {
        g_hx[group * (HID * GROUP_B) + (h0 + (idx >> 4)) * GROUP_B + (idx & 15)] = 0.0f;
    }
    __threadfence();
    CLUSTER_SYNC_();

    const int warp    = tid >> 5;
    const int h_local = tid & 31;
    const int bq      = warp & 3;    // batch quad: batches bq*4 .. bq*4+3
    const int kh      = warp >> 2;   // K half: 0 or 1

    const float* wp = w_sm  + (kh * 128) * 128 + h_local * 4;
    const float* hp = hx_sm + (kh * 128) * 16  + bq * 4;
    const int    rid = bq * 32 + h_local;          // 0..127 (per kh group)

    float cx[4] = {0.f, 0.f, 0.f, 0.f};
    int p = 0;

    const float4 wx4 = wx4_sm[h_local];
    const float4 bb4 = b4_sm[h_local];

    for (int t = 0; t < SEQ; ++t) {
        // ---- stage hx (256x16) for this group into smem (L2-coherent loads)
        const float* src = g_hx + p * (BATCH * HID) + group * (HID * GROUP_B);
#pragma unroll
        for (int j = 0; j < 4; ++j) {
            int idx = j * 1024 + tid * 4;
            float4 v = __ldcg((const float4*)(src + idx));
            *(float4*)(hx_sm + idx) = v;
        }
        if (tid < GROUP_B) xs[tid] = __ldg(xfeat + (b0 + tid) * SEQ + t);
        __syncthreads();

        // ---- init accumulators: kh==0 warps carry bias + wx*x, kh==1 carry 0
        float acc[16];
        if (kh == 0) {
#pragma unroll
            for (int b = 0; b < 4; ++b) {
                float xb = xs[bq * 4 + b];
                acc[b*4+0] = fmaf(wx4.x, xb, bb4.x);
                acc[b*4+1] = fmaf(wx4.y, xb, bb4.y);
                acc[b*4+2] = fmaf(wx4.z, xb, bb4.z);
                acc[b*4+3] = fmaf(wx4.w, xb, bb4.w);
            }
        } else {
#pragma unroll
            for (int i = 0; i < 16; ++i) acc[i] = 0.0f;
        }

        // ---- main GEMV slice: 128 k-steps, 16 FFMA each
#pragma unroll 4
        for (int k = 0; k < 128; ++k) {
            float4 w4 = *(const float4*)(wp + k * 128);  // f,i,g,o weights @ (k,h)
            float4 h4 = *(const float4*)(hp + k * 16);   // hx[k][4 batches] (bcast)
            acc[0]  = fmaf(w4.x, h4.x, acc[0]);
            acc[1]  = fmaf(w4.y, h4.x, acc[1]);
            acc[2]  = fmaf(w4.z, h4.x, acc[2]);
            acc[3]  = fmaf(w4.w, h4.x, acc[3]);
            acc[4]  = fmaf(w4.x, h4.y, acc[4]);
            acc[5]  = fmaf(w4.y, h4.y, acc[5]);
            acc[6]  = fmaf(w4.z, h4.y, acc[6]);
            acc[7]  = fmaf(w4.w, h4.y, acc[7]);
            acc[8]  = fmaf(w4.x, h4.z, acc[8]);
            acc[9]  = fmaf(w4.y, h4.z, acc[9]);
            acc[10] = fmaf(w4.z, h4.z, acc[10]);
            acc[11] = fmaf(w4.w, h4.z, acc[11]);
            acc[12] = fmaf(w4.x, h4.w, acc[12]);
            acc[13] = fmaf(w4.y, h4.w, acc[13]);
            acc[14] = fmaf(w4.z, h4.w, acc[14]);
            acc[15] = fmaf(w4.w, h4.w, acc[15]);
        }

        // ---- cross-K reduction (kh==1 -> smem -> kh==0), conflict-free layout
        if (kh == 1) {
#pragma unroll
            for (int i = 0; i < 16; ++i) red_sm[i * 128 + rid] = acc[i];
        }
        __syncthreads();

        if (kh == 0) {
#pragma unroll
            for (int i = 0; i < 16; ++i) acc[i] += red_sm[i * 128 + rid];

            float hx4[4];
#pragma unroll
            for (int b = 0; b < 4; ++b) {
                float f  = fast_sigmoid(acc[b*4+0]);
                float i_ = fast_sigmoid(acc[b*4+1]);
                float g_ = fast_tanh   (acc[b*4+2]);
                float o  = fast_sigmoid(acc[b*4+3]);
                cx[b] = fmaf(f, cx[b], i_ * g_);
                hx4[b] = o * fast_tanh(cx[b]);
            }
            float* dst = g_hx + (p ^ 1) * (BATCH * HID) + group * (HID * GROUP_B)
                       + (h0 + h_local) * GROUP_B + bq * 4;
            __stcg((float4*)dst, make_float4(hx4[0], hx4[1], hx4[2], hx4[3]));
        }
        __threadfence();
        CLUSTER_SYNC_();
        p ^= 1;
    }

    // ---- head: logits[b] = hx . w_head + b_head (rank-0 CTA per cluster)
    if (ctarank == 0) {
        const float* src = g_hx + p * (BATCH * HID) + group * (HID * GROUP_B);
        const int b_l  = tid >> 4;
        const int part = tid & 15;
        float s = 0.0f;
#pragma unroll
        for (int kk = 0; kk < 16; ++kk) {
            int h = part * 16 + kk;
            s = fmaf(__ldcg(src + h * GROUP_B + b_l), __ldg(w_head + h), s);
        }
        s += __shfl_xor_sync(0xffffffffu, s, 8);
        s += __shfl_xor_sync(0xffffffffu, s, 4);
        s += __shfl_xor_sync(0xffffffffu, s, 2);
        s += __shfl_xor_sync(0xffffffffu, s, 1);
        if (part == 0) logits[b0 + b_l] = s + __ldg(b_head);
    }
}

// ======================= launch ===========================================

extern "C" void kernel_launch(void* const* d_in, const int* in_sizes, int n_in,
                              void* d_out, int out_size)
{
    const float* x      = (const float*)d_in[0];
    const float* w1     = (const float*)d_in[1];
    const float* b1     = (const float*)d_in[2];
    const float* w2     = (const float*)d_in[3];
    const float* b2     = (const float*)d_in[4];
    const float* w3     = (const float*)d_in[5];
    const float* b3     = (const float*)d_in[6];
    const float* w4     = (const float*)d_in[7];
    const float* b4     = (const float*)d_in[8];
    const float* w5     = (const float*)d_in[9];
    const float* b5     = (const float*)d_in[10];
    const float* w6     = (const float*)d_in[11];
    const float* b6     = (const float*)d_in[12];
    const float* w7     = (const float*)d_in[13];
    const float* b7     = (const float*)d_in[14];
    const float* w_f    = (const float*)d_in[15];
    const float* b_f    = (const float*)d_in[16];
    const float* w_i    = (const float*)d_in[17];
    const float* b_i    = (const float*)d_in[18];
    const float* w_g    = (const float*)d_in[19];
    const float* b_g    = (const float*)d_in[20];
    const float* w_o    = (const float*)d_in[21];
    const float* b_o    = (const float*)d_in[22];
    const float* w_head = (const float*)d_in[23];
    const float* b_head = (const float*)d_in[24];

    float* out = (float*)d_out;

    cnn_kernel<<<(BATCH * SEQ) / 256, 256>>>(x, w1, b1, w2, b2, w3, b3, w4, b4,
                                             w5, b5, w6, b6, w7, b7, out);

    cudaFuncSetAttribute(lstm_kernel, cudaFuncAttributeMaxDynamicSharedMemorySize,
                         SMEM_BYTES);
    lstm_kernel<<<128, LSTM_THREADS, SMEM_BYTES>>>(
        out, w_f, b_f, w_i, b_i, w_g, b_g, w_o, b_o, w_head, b_head,
        out + BATCH * SEQ);
}

// round 5
// speedup vs baseline: 3.2745x; 2.7671x over previous
#include <cuda_runtime.h>
#include <cuda_bf16.h>
#include <cstdint>
#include <math.h>

// ---------------------------------------------------------------------------
// HybridQCNNQLSTM : B=256, S=1024, H=256
//   Stage 1: per-element MLP 1->16->16->12->8->4->4 (tanh) -> 1 (linear)
//   Stage 2: LSTM via mma.sync m16n8k16 bf16 (hi/lo split x3, fp32 acc)
//   out = [cnn_features (B*S) | logits (B)]
// ---------------------------------------------------------------------------

#define BATCH 256
#define SEQ   1024
#define HID   256

// ======================= Stage 1: CNN MLP kernel ===========================

template<int DIN, int DOUT>
__device__ __forceinline__ void layer_tanh(const float* __restrict__ w,
                                           const float* __restrict__ b,
                                           const float* in, float* out) {
#pragma unroll
    for (int o = 0; o < DOUT; ++o) {
        float s = b[o];
#pragma unroll
        for (int i = 0; i < DIN; ++i) s = fmaf(w[o * DIN + i], in[i], s);
        out[o] = tanhf(s);
    }
}

__global__ void __launch_bounds__(256) cnn_kernel(
    const float* __restrict__ x,
    const float* __restrict__ w1, const float* __restrict__ b1,
    const float* __restrict__ w2, const float* __restrict__ b2,
    const float* __restrict__ w3, const float* __restrict__ b3,
    const float* __restrict__ w4, const float* __restrict__ b4,
    const float* __restrict__ w5, const float* __restrict__ b5,
    const float* __restrict__ w6, const float* __restrict__ b6,
    const float* __restrict__ w7, const float* __restrict__ b7,
    float* __restrict__ out)
{
    __shared__ float ws[673];
    const int tid = threadIdx.x;
    {
        const float* srcs[14] = {w1,b1,w2,b2,w3,b3,w4,b4,w5,b5,w6,b6,w7,b7};
        const int    lens[14] = {16,16,256,16,192,12,96,8,32,4,16,4,4,1};
        int off = 0;
        for (int s = 0; s < 14; ++s) {
            for (int i = tid; i < lens[s]; i += 256) ws[off + i] = srcs[s][i];
            off += lens[s];
        }
    }
    __syncthreads();

    const int e = blockIdx.x * 256 + tid;
    float v = x[e];
    float h1[16], h2[16], h3[12], h4[8], h5[4], h6[4];
    layer_tanh<1, 16>(ws + 0,   ws + 16,  &v, h1);
    layer_tanh<16,16>(ws + 32,  ws + 288, h1, h2);
    layer_tanh<16,12>(ws + 304, ws + 496, h2, h3);
    layer_tanh<12, 8>(ws + 508, ws + 604, h3, h4);
    layer_tanh<8,  4>(ws + 612, ws + 644, h4, h5);
    layer_tanh<4,  4>(ws + 648, ws + 664, h5, h6);
    float o = ws[672];
#pragma unroll
    for (int i = 0; i < 4; ++i) o = fmaf(ws[668 + i], h6[i], o);
    out[e] = o;
}

// ======================= Stage 2: LSTM (mma.sync) ==========================
//
// 8 groups x 8-CTA clusters (64 CTAs). Group g: batches [32g, 32g+32).
// CTA rank r: gate-rows [0,128) for hidden slice [32r,32r+32),
// row = gate*32 + h_local (gate-major).
// A (weights): bf16 hi/lo fragments resident in REGISTERS (built once).
// B (hx):      [n=32][k=256 pad 264] bf16, hi+lo, staged per step from a
//              double-buffered global image with identical layout.
// mma.sync.aligned.m16n8k16.row.col.f32.bf16.bf16.f32, 3 passes.

#define GROUPS       8
#define GROUP_B      32
#define LSTM_CTAS    64
#define LSTM_THREADS 256

#define KPAD        264                     // bf16 per B row (k padded)
#define B_ROW_BYTES (KPAD * 2)              // 528
#define IMG_HALF    (GROUP_B * B_ROW_BYTES) // 16896 (hi or lo)
#define IMG_BYTES   (2 * IMG_HALF)          // 33792
#define IMG_U4      (IMG_BYTES / 16)        // 2112

// smem byte offsets
#define BHI_OFF    0
#define BLO_OFF    IMG_HALF
#define TRANS_OFF  IMG_BYTES                // 128 rows * 34 * 4 = 17408
#define WXB_OFF    (TRANS_OFF + 17408)      // [4][32] f32
#define BIAS_OFF   (WXB_OFF + 512)
#define XS_OFF     (BIAS_OFF + 512)
#define SMEM_BYTES (XS_OFF + 128)

#define TR_STRIDE  34                       // floats per trans row
#define TR_G       (32 * TR_STRIDE)         // gate stride in trans

__device__ uint4 g_hximg4[2 * GROUPS * IMG_U4];   // ~540 KB
__device__ float g_hxf32[GROUPS * GROUP_B * HID];

__device__ __forceinline__ float fast_sigmoid(float v) {
    return __fdividef(1.0f, 1.0f + __expf(-v));
}
__device__ __forceinline__ float fast_tanh(float v) {
    return 1.0f - __fdividef(2.0f, __expf(2.0f * v) + 1.0f);
}
__device__ __forceinline__ uint32_t pack2bf(float lo, float hi) {
    __nv_bfloat162 t = __floats2bfloat162_rn(lo, hi);
    return *(uint32_t*)&t;
}

__device__ __forceinline__ void mma16816(float* c, const uint32_t* a,
                                         uint32_t b0, uint32_t b1) {
    asm volatile(
        "mma.sync.aligned.m16n8k16.row.col.f32.bf16.bf16.f32 "
        "{%0,%1,%2,%3}, {%4,%5,%6,%7}, {%8,%9}, {%0,%1,%2,%3};"
        : "+f"(c[0]), "+f"(c[1]), "+f"(c[2]), "+f"(c[3])
        : "r"(a[0]), "r"(a[1]), "r"(a[2]), "r"(a[3]), "r"(b0), "r"(b1));
}

#define CLUSTER_SYNC_() do { \
    asm volatile("barrier.cluster.arrive.aligned;" ::: "memory"); \
    asm volatile("barrier.cluster.wait.aligned;"   ::: "memory"); \
} while (0)

__global__ void __launch_bounds__(LSTM_THREADS, 1) __cluster_dims__(8, 1, 1)
lstm_kernel(const float* __restrict__ xfeat,
            const float* __restrict__ w_f, const float* __restrict__ b_f,
            const float* __restrict__ w_i, const float* __restrict__ b_i,
            const float* __restrict__ w_g, const float* __restrict__ b_g,
            const float* __restrict__ w_o, const float* __restrict__ b_o,
            const float* __restrict__ w_head, const float* __restrict__ b_head,
            float* __restrict__ logits)
{
    extern __shared__ __align__(16) uint8_t sm8[];
    float* trans   = (float*)(sm8 + TRANS_OFF);
    float* wxb_sm  = (float*)(sm8 + WXB_OFF);
    float* bias_sm = (float*)(sm8 + BIAS_OFF);
    float* xs      = (float*)(sm8 + XS_OFF);

    const int tid     = threadIdx.x;
    const int warp    = tid >> 5;
    const int lane    = tid & 31;
    const int ctarank = blockIdx.x & 7;
    const int group   = blockIdx.x >> 3;
    const int h0      = ctarank * 32;
    const int b0      = group * GROUP_B;

    const float* Wg[4] = {w_f, w_i, w_g, w_o};
    const float* Bg[4] = {b_f, b_i, b_g, b_o};

    if (tid < 128) {
        int g = tid >> 5, h = tid & 31;
        wxb_sm[g * 32 + h]  = Wg[g][(h0 + h) * 257];
        bias_sm[g * 32 + h] = Bg[g][h0 + h];
    }

    // ---- build A fragments in registers (bf16 hi/lo), rows r0 & r0+8
    uint32_t ahi[64], alo[64];
    {
        const int r0 = warp * 16 + (lane >> 2);
        const int r1 = r0 + 8;
        const int g0 = r0 >> 5, hh0 = r0 & 31;
        const int g1 = r1 >> 5, hh1 = r1 & 31;
        const float* row0 = Wg[g0] + (h0 + hh0) * 257 + 1;
        const float* row1 = Wg[g1] + (h0 + hh1) * 257 + 1;
        const int kb = (lane & 3) * 2;
#pragma unroll
        for (int kc = 0; kc < 16; ++kc) {
            int k0 = kc * 16 + kb;
            float v00 = row0[k0],     v01 = row0[k0 + 1];
            float v10 = row1[k0],     v11 = row1[k0 + 1];
            float v02 = row0[k0 + 8], v03 = row0[k0 + 9];
            float v12 = row1[k0 + 8], v13 = row1[k0 + 9];
            float h00 = __bfloat162float(__float2bfloat16(v00));
            float h01 = __bfloat162float(__float2bfloat16(v01));
            float h10 = __bfloat162float(__float2bfloat16(v10));
            float h11 = __bfloat162float(__float2bfloat16(v11));
            float h02 = __bfloat162float(__float2bfloat16(v02));
            float h03 = __bfloat162float(__float2bfloat16(v03));
            float h12 = __bfloat162float(__float2bfloat16(v12));
            float h13 = __bfloat162float(__float2bfloat16(v13));
            ahi[kc * 4 + 0] = pack2bf(h00, h01);
            ahi[kc * 4 + 1] = pack2bf(h10, h11);
            ahi[kc * 4 + 2] = pack2bf(h02, h03);
            ahi[kc * 4 + 3] = pack2bf(h12, h13);
            alo[kc * 4 + 0] = pack2bf(v00 - h00, v01 - h01);
            alo[kc * 4 + 1] = pack2bf(v10 - h10, v11 - h11);
            alo[kc * 4 + 2] = pack2bf(v02 - h02, v03 - h03);
            alo[kc * 4 + 3] = pack2bf(v12 - h12, v13 - h13);
        }
    }

    // ---- zero hx image buffer 0 (this CTA's 1/8 of the group's image)
    {
        uint4 z = make_uint4(0, 0, 0, 0);
        uint4* dst = g_hximg4 + group * IMG_U4 + ctarank * (IMG_U4 / 8);
        for (int i = tid; i < IMG_U4 / 8; i += LSTM_THREADS) dst[i] = z;
    }
    __syncthreads();
    __threadfence();
    CLUSTER_SYNC_();

    // per-thread B fragment base (conflict-free: 264-pad => bank = 4*(l/4)+(l%4))
    const uint32_t b_thread_off = (uint32_t)((lane >> 2) * B_ROW_BYTES + (lane & 3) * 4);
    const int b_l = tid >> 3;   // epilogue batch 0..31
    const int hq  = tid & 7;    // epilogue h-quad 0..7
    float cx[4] = {0.f, 0.f, 0.f, 0.f};
    int p = 0;

#pragma unroll 1
    for (int t = 0; t < SEQ; ++t) {
        // ---- stage B image (hi+lo, 33 KB) global -> smem (identical layout)
        {
            const uint4* src = g_hximg4 + (p * GROUPS + group) * IMG_U4;
            uint4* dst = (uint4*)sm8;
            for (int i = tid; i < IMG_U4; i += LSTM_THREADS)
                dst[i] = __ldcg(src + i);
        }
        if (tid < GROUP_B) xs[tid] = __ldg(xfeat + (b0 + tid) * SEQ + t);
        __syncthreads();

        // ---- MMA: D[128,32] = Whi*Hhi + Whi*Hlo + Wlo*Hhi (fp32 acc)
        float acc[4][4];
#pragma unroll
        for (int nt = 0; nt < 4; ++nt)
#pragma unroll
            for (int j = 0; j < 4; ++j) acc[nt][j] = 0.0f;

#pragma unroll
        for (int nt = 0; nt < 4; ++nt) {
            const uint8_t* bh = sm8 + BHI_OFF + nt * 8 * B_ROW_BYTES + b_thread_off;
            const uint8_t* bl = sm8 + BLO_OFF + nt * 8 * B_ROW_BYTES + b_thread_off;
#pragma unroll
            for (int kc = 0; kc < 16; ++kc) {
                uint32_t bh0 = *(const uint32_t*)(bh + kc * 32);
                uint32_t bh1 = *(const uint32_t*)(bh + kc * 32 + 16);
                uint32_t bl0 = *(const uint32_t*)(bl + kc * 32);
                uint32_t bl1 = *(const uint32_t*)(bl + kc * 32 + 16);
                mma16816(acc[nt], ahi + kc * 4, bh0, bh1);
                mma16816(acc[nt], alo + kc * 4, bh0, bh1);
                mma16816(acc[nt], ahi + kc * 4, bl0, bl1);
            }
        }

        // ---- write accumulators to trans[row][b] (row = gate*32 + h_local)
        {
            const int r0 = warp * 16 + (lane >> 2);
            const int r1 = r0 + 8;
            const int cc = (lane & 3) * 2;
#pragma unroll
            for (int nt = 0; nt < 4; ++nt) {
                int c = nt * 8 + cc;
                *(float2*)(trans + r0 * TR_STRIDE + c) = make_float2(acc[nt][0], acc[nt][1]);
                *(float2*)(trans + r1 * TR_STRIDE + c) = make_float2(acc[nt][2], acc[nt][3]);
            }
        }
        __syncthreads();

        // ---- epilogue: thread = (batch b_l, h-quad hq); cx in registers
        {
            float xb = xs[b_l];
            float vout[4];
#pragma unroll
            for (int j = 0; j < 4; ++j) {
                int h = hq * 4 + j;
                float pf = trans[0 * TR_G + h * TR_STRIDE + b_l] + fmaf(wxb_sm[0*32+h], xb, bias_sm[0*32+h]);
                float pi = trans[1 * TR_G + h * TR_STRIDE + b_l] + fmaf(wxb_sm[1*32+h], xb, bias_sm[1*32+h]);
                float pg = trans[2 * TR_G + h * TR_STRIDE + b_l] + fmaf(wxb_sm[2*32+h], xb, bias_sm[2*32+h]);
                float po = trans[3 * TR_G + h * TR_STRIDE + b_l] + fmaf(wxb_sm[3*32+h], xb, bias_sm[3*32+h]);
                float f  = fast_sigmoid(pf);
                float ii = fast_sigmoid(pi);
                float gg = fast_tanh(pg);
                float oo = fast_sigmoid(po);
                cx[j] = fmaf(f, cx[j], ii * gg);
                vout[j] = oo * fast_tanh(cx[j]);
            }
            // pack hx hi/lo into the B image layout: [b][k=h], k contiguous
            float h0f = __bfloat162float(__float2bfloat16(vout[0]));
            float h1f = __bfloat162float(__float2bfloat16(vout[1]));
            float h2f = __bfloat162float(__float2bfloat16(vout[2]));
            float h3f = __bfloat162float(__float2bfloat16(vout[3]));
            uint2 hw = make_uint2(pack2bf(h0f, h1f), pack2bf(h2f, h3f));
            uint2 lw = make_uint2(pack2bf(vout[0] - h0f, vout[1] - h1f),
                                  pack2bf(vout[2] - h2f, vout[3] - h3f));
            int hg = h0 + hq * 4;
            uint8_t* img = (uint8_t*)g_hximg4 + ((p ^ 1) * GROUPS + group) * IMG_BYTES;
            uint32_t off = (uint32_t)(b_l * B_ROW_BYTES + hg * 2);
            __stcg((uint2*)(img + off),            hw);
            __stcg((uint2*)(img + IMG_HALF + off), lw);

            if (t == SEQ - 1) {
                *(float4*)(g_hxf32 + (group * GROUP_B + b_l) * HID + hg) =
                    make_float4(vout[0], vout[1], vout[2], vout[3]);
            }
        }
        __threadfence();
        CLUSTER_SYNC_();
        p ^= 1;
    }

    // ---- head (rank-0 CTA per cluster): logits[b] = hx . w_head + b_head
    if (ctarank == 0) {
        const int bb   = tid >> 3;   // 0..31
        const int part = tid & 7;    // 0..7
        const float* src = g_hxf32 + (group * GROUP_B + bb) * HID + part * 32;
        float s = 0.0f;
#pragma unroll
        for (int kk = 0; kk < 32; ++kk)
            s = fmaf(src[kk], __ldg(w_head + part * 32 + kk), s);
        s += __shfl_xor_sync(0xffffffffu, s, 4);
        s += __shfl_xor_sync(0xffffffffu, s, 2);
        s += __shfl_xor_sync(0xffffffffu, s, 1);
        if (part == 0) logits[b0 + bb] = s + __ldg(b_head);
    }
}

// ======================= launch ===========================================

extern "C" void kernel_launch(void* const* d_in, const int* in_sizes, int n_in,
                              void* d_out, int out_size)
{
    const float* x      = (const float*)d_in[0];
    const float* w1     = (const float*)d_in[1];
    const float* b1     = (const float*)d_in[2];
    const float* w2     = (const float*)d_in[3];
    const float* b2     = (const float*)d_in[4];
    const float* w3     = (const float*)d_in[5];
    const float* b3     = (const float*)d_in[6];
    const float* w4     = (const float*)d_in[7];
    const float* b4     = (const float*)d_in[8];
    const float* w5     = (const float*)d_in[9];
    const float* b5     = (const float*)d_in[10];
    const float* w6     = (const float*)d_in[11];
    const float* b6     = (const float*)d_in[12];
    const float* w7     = (const float*)d_in[13];
    const float* b7     = (const float*)d_in[14];
    const float* w_f    = (const float*)d_in[15];
    const float* b_f    = (const float*)d_in[16];
    const float* w_i    = (const float*)d_in[17];
    const float* b_i    = (const float*)d_in[18];
    const float* w_g    = (const float*)d_in[19];
    const float* b_g    = (const float*)d_in[20];
    const float* w_o    = (const float*)d_in[21];
    const float* b_o    = (const float*)d_in[22];
    const float* w_head = (const float*)d_in[23];
    const float* b_head = (const float*)d_in[24];

    float* out = (float*)d_out;

    cnn_kernel<<<(BATCH * SEQ) / 256, 256>>>(x, w1, b1, w2, b2, w3, b3, w4, b4,
                                             w5, b5, w6, b6, w7, b7, out);

    cudaFuncSetAttribute(lstm_kernel, cudaFuncAttributeMaxDynamicSharedMemorySize,
                         SMEM_BYTES);
    lstm_kernel<<<LSTM_CTAS, LSTM_THREADS, SMEM_BYTES>>>(
        out, w_f, b_f, w_i, b_i, w_g, b_g, w_o, b_o, w_head, b_head,
        out + BATCH * SEQ);
}

// round 6
// speedup vs baseline: 3.3175x; 1.0131x over previous
#include <cuda_runtime.h>
#include <cuda_bf16.h>
#include <cstdint>
#include <math.h>

// ---------------------------------------------------------------------------
// HybridQCNNQLSTM : B=256, S=1024, H=256
//   Stage 1: per-element MLP 1->16->16->12->8->4->4 (tanh) -> 1 (linear)
//   Stage 2: LSTM via mma.sync m16n8k16 bf16 (hi/lo split x3, fp32 acc)
//            512 thr/CTA, k-split warps, cp.async stage, packeted hi/lo B
//   out = [cnn_features (B*S) | logits (B)]
// ---------------------------------------------------------------------------

#define BATCH 256
#define SEQ   1024
#define HID   256

// ======================= Stage 1: CNN MLP kernel ===========================

template<int DIN, int DOUT>
__device__ __forceinline__ void layer_tanh(const float* __restrict__ w,
                                           const float* __restrict__ b,
                                           const float* in, float* out) {
#pragma unroll
    for (int o = 0; o < DOUT; ++o) {
        float s = b[o];
#pragma unroll
        for (int i = 0; i < DIN; ++i) s = fmaf(w[o * DIN + i], in[i], s);
        out[o] = tanhf(s);
    }
}

__global__ void __launch_bounds__(256) cnn_kernel(
    const float* __restrict__ x,
    const float* __restrict__ w1, const float* __restrict__ b1,
    const float* __restrict__ w2, const float* __restrict__ b2,
    const float* __restrict__ w3, const float* __restrict__ b3,
    const float* __restrict__ w4, const float* __restrict__ b4,
    const float* __restrict__ w5, const float* __restrict__ b5,
    const float* __restrict__ w6, const float* __restrict__ b6,
    const float* __restrict__ w7, const float* __restrict__ b7,
    float* __restrict__ out)
{
    __shared__ float ws[673];
    const int tid = threadIdx.x;
    {
        const float* srcs[14] = {w1,b1,w2,b2,w3,b3,w4,b4,w5,b5,w6,b6,w7,b7};
        const int    lens[14] = {16,16,256,16,192,12,96,8,32,4,16,4,4,1};
        int off = 0;
        for (int s = 0; s < 14; ++s) {
            for (int i = tid; i < lens[s]; i += 256) ws[off + i] = srcs[s][i];
            off += lens[s];
        }
    }
    __syncthreads();

    const int e = blockIdx.x * 256 + tid;
    float v = x[e];
    float h1[16], h2[16], h3[12], h4[8], h5[4], h6[4];
    layer_tanh<1, 16>(ws + 0,   ws + 16,  &v, h1);
    layer_tanh<16,16>(ws + 32,  ws + 288, h1, h2);
    layer_tanh<16,12>(ws + 304, ws + 496, h2, h3);
    layer_tanh<12, 8>(ws + 508, ws + 604, h3, h4);
    layer_tanh<8,  4>(ws + 612, ws + 644, h4, h5);
    layer_tanh<4,  4>(ws + 648, ws + 664, h5, h6);
    float o = ws[672];
#pragma unroll
    for (int i = 0; i < 4; ++i) o = fmaf(ws[668 + i], h6[i], o);
    out[e] = o;
}

// ======================= Stage 2: LSTM (mma.sync, v5) ======================
//
// 8 groups x 8-CTA clusters (64 CTAs), 512 threads (16 warps).
// CTA rank r: gate-rows [0,128) for hidden slice [32r,32r+32),
//             row = gate*32 + h_local (gate-major).
// Warp w: mrow = w&7 (16 rows), kh = w>>3 (k half: kc 8*kh .. 8*kh+7).
// A (weights): bf16 hi/lo in registers (64 regs), built once.
// B (hx): packet layout per (n,kc,c): 16B = {hi_b0, hi_b1, lo_b0, lo_b1};
//   row n stride 1088 B. Double-buffered global image, identical layout,
//   staged per step via cp.async. Epilogue writes packets directly.
// Cross-K reduction + gate transpose through one smem buffer.

#define GROUPS       8
#define GROUP_B      32
#define LSTM_CTAS    64
#define LSTM_THREADS 512

#define ROW_BYTES  1088                     // 16 kc * 64B + 64B pad
#define IMG_BYTES  (GROUP_B * ROW_BYTES)    // 34816
#define IMG_U4     (IMG_BYTES / 16)         // 2176

// smem byte offsets
#define B_OFF      0                        // 34816
#define RED_OFF    34816                    // 128 * 33 * 4 = 16896
#define WXB_OFF    51712                    // [4][32] f32
#define BIAS_OFF   52224                    // [4][32] f32
#define XS_OFF     52736                    // [32] f32
#define SMEM_BYTES 52864

#define RED_STR    33                       // floats per red row

__device__ uint4 g_hximg4[2 * GROUPS * IMG_U4];   // ~557 KB
__device__ float g_hxf32[GROUPS * GROUP_B * HID];

__device__ __forceinline__ float fast_sigmoid(float v) {
    return __fdividef(1.0f, 1.0f + __expf(-v));
}
__device__ __forceinline__ float fast_tanh(float v) {
    return 1.0f - __fdividef(2.0f, __expf(2.0f * v) + 1.0f);
}
__device__ __forceinline__ uint32_t pack2bf(float lo, float hi) {
    __nv_bfloat162 t = __floats2bfloat162_rn(lo, hi);
    return *(uint32_t*)&t;
}

__device__ __forceinline__ void mma16816(float* c, const uint32_t* a,
                                         uint32_t b0, uint32_t b1) {
    asm volatile(
        "mma.sync.aligned.m16n8k16.row.col.f32.bf16.bf16.f32 "
        "{%0,%1,%2,%3}, {%4,%5,%6,%7}, {%8,%9}, {%0,%1,%2,%3};"
        : "+f"(c[0]), "+f"(c[1]), "+f"(c[2]), "+f"(c[3])
        : "r"(a[0]), "r"(a[1]), "r"(a[2]), "r"(a[3]), "r"(b0), "r"(b1));
}

#define CLUSTER_SYNC_() do { \
    asm volatile("barrier.cluster.arrive.aligned;" ::: "memory"); \
    asm volatile("barrier.cluster.wait.aligned;"   ::: "memory"); \
} while (0)

#define CP_ASYNC_16(smem_u32, gptr) \
    asm volatile("cp.async.cg.shared.global [%0], [%1], 16;" \
        :: "r"(smem_u32), "l"(gptr) : "memory")
#define CP_ASYNC_COMMIT() asm volatile("cp.async.commit_group;" ::: "memory")
#define CP_ASYNC_WAIT0()  asm volatile("cp.async.wait_group 0;" ::: "memory")

__global__ void __launch_bounds__(LSTM_THREADS, 1) __cluster_dims__(8, 1, 1)
lstm_kernel(const float* __restrict__ xfeat,
            const float* __restrict__ w_f, const float* __restrict__ b_f,
            const float* __restrict__ w_i, const float* __restrict__ b_i,
            const float* __restrict__ w_g, const float* __restrict__ b_g,
            const float* __restrict__ w_o, const float* __restrict__ b_o,
            const float* __restrict__ w_head, const float* __restrict__ b_head,
            float* __restrict__ logits)
{
    extern __shared__ __align__(16) uint8_t sm8[];
    float* red     = (float*)(sm8 + RED_OFF);
    float* wxb_sm  = (float*)(sm8 + WXB_OFF);
    float* bias_sm = (float*)(sm8 + BIAS_OFF);
    float* xs      = (float*)(sm8 + XS_OFF);

    uint32_t smem_u32;
    asm("{ .reg .u64 t; cvta.to.shared.u64 t, %1; cvt.u32.u64 %0, t; }"
        : "=r"(smem_u32) : "l"(sm8));

    const int tid     = threadIdx.x;
    const int warp    = tid >> 5;
    const int lane    = tid & 31;
    const int ctarank = blockIdx.x & 7;
    const int group   = blockIdx.x >> 3;
    const int h0      = ctarank * 32;
    const int b0      = group * GROUP_B;

    const int mrow = warp & 7;     // M-tile (16 rows)
    const int kh   = warp >> 3;    // k-half

    const float* Wg[4] = {w_f, w_i, w_g, w_o};
    const float* Bg[4] = {b_f, b_i, b_g, b_o};

    if (tid < 128) {
        int g = tid >> 5, h = tid & 31;
        wxb_sm[g * 32 + h]  = Wg[g][(h0 + h) * 257];
        bias_sm[g * 32 + h] = Bg[g][h0 + h];
    }

    // ---- build A fragments (this warp's k-half): 8 kc x 4 regs x hi/lo
    uint32_t ahi[32], alo[32];
    {
        const int r0 = mrow * 16 + (lane >> 2);
        const int r1 = r0 + 8;
        const float* row0 = Wg[r0 >> 5] + (h0 + (r0 & 31)) * 257 + 1;
        const float* row1 = Wg[r1 >> 5] + (h0 + (r1 & 31)) * 257 + 1;
        const int kb = (lane & 3) * 2;
#pragma unroll
        for (int kc = 0; kc < 8; ++kc) {
            int k0 = (kh * 8 + kc) * 16 + kb;
            float v00 = row0[k0],     v01 = row0[k0 + 1];
            float v10 = row1[k0],     v11 = row1[k0 + 1];
            float v02 = row0[k0 + 8], v03 = row0[k0 + 9];
            float v12 = row1[k0 + 8], v13 = row1[k0 + 9];
            float h00 = __bfloat162float(__float2bfloat16(v00));
            float h01 = __bfloat162float(__float2bfloat16(v01));
            float h10 = __bfloat162float(__float2bfloat16(v10));
            float h11 = __bfloat162float(__float2bfloat16(v11));
            float h02 = __bfloat162float(__float2bfloat16(v02));
            float h03 = __bfloat162float(__float2bfloat16(v03));
            float h12 = __bfloat162float(__float2bfloat16(v12));
            float h13 = __bfloat162float(__float2bfloat16(v13));
            ahi[kc * 4 + 0] = pack2bf(h00, h01);
            ahi[kc * 4 + 1] = pack2bf(h10, h11);
            ahi[kc * 4 + 2] = pack2bf(h02, h03);
            ahi[kc * 4 + 3] = pack2bf(h12, h13);
            alo[kc * 4 + 0] = pack2bf(v00 - h00, v01 - h01);
            alo[kc * 4 + 1] = pack2bf(v10 - h10, v11 - h11);
            alo[kc * 4 + 2] = pack2bf(v02 - h02, v03 - h03);
            alo[kc * 4 + 3] = pack2bf(v12 - h12, v13 - h13);
        }
    }

    // ---- zero hx image buffer 0 (this CTA's 1/8 of group's image)
    {
        uint4 z = make_uint4(0, 0, 0, 0);
        uint4* dst = g_hximg4 + group * IMG_U4 + ctarank * (IMG_U4 / 8);
        for (int i = tid; i < IMG_U4 / 8; i += LSTM_THREADS) dst[i] = z;
    }
    __syncthreads();
    CLUSTER_SYNC_();   // arrive has release semantics (orders the zero stores)

    // per-thread B packet base within a row-block of 8 n
    const uint32_t b_lane_off = (uint32_t)((lane >> 2) * ROW_BYTES + (lane & 3) * 16);
    // epilogue mapping: b = tid>>4, h-pair hp = tid&15
    const int ep_b  = tid >> 4;
    const int ep_hp = tid & 15;
    float cx[2] = {0.f, 0.f};
    int p = 0;

#pragma unroll 1
    for (int t = 0; t < SEQ; ++t) {
        // ---- stage B image (34 KB) via cp.async (identical layout)
        {
            const uint8_t* src = (const uint8_t*)g_hximg4
                               + (size_t)(p * GROUPS + group) * IMG_BYTES;
            for (int i = tid; i < IMG_U4; i += LSTM_THREADS)
                CP_ASYNC_16(smem_u32 + B_OFF + i * 16, src + i * 16);
            CP_ASYNC_COMMIT();
        }
        if (tid < GROUP_B) xs[tid] = __ldg(xfeat + (b0 + tid) * SEQ + t);
        CP_ASYNC_WAIT0();
        __syncthreads();

        // ---- MMA: this warp's k-half, 3 passes fused per packet
        float acc[4][4];
#pragma unroll
        for (int nt = 0; nt < 4; ++nt)
#pragma unroll
            for (int j = 0; j < 4; ++j) acc[nt][j] = 0.0f;

#pragma unroll
        for (int nt = 0; nt < 4; ++nt) {
            const uint8_t* bp = sm8 + B_OFF + nt * 8 * ROW_BYTES + b_lane_off
                              + kh * 8 * 64;
#pragma unroll
            for (int kc = 0; kc < 8; ++kc) {
                uint4 pk = *(const uint4*)(bp + kc * 64);
                mma16816(acc[nt], ahi + kc * 4, pk.x, pk.y);   // Whi * Hhi
                mma16816(acc[nt], alo + kc * 4, pk.x, pk.y);   // Wlo * Hhi
                mma16816(acc[nt], ahi + kc * 4, pk.z, pk.w);   // Whi * Hlo
            }
        }

        // ---- cross-K reduction into red[row][col] (row = gate*32+h, col = b)
        {
            const int r0 = mrow * 16 + (lane >> 2);
            const int r1 = r0 + 8;
            const int c0 = (lane & 3) * 2;
            if (kh == 1) {
#pragma unroll
                for (int nt = 0; nt < 4; ++nt) {
                    int c = nt * 8 + c0;
                    red[r0 * RED_STR + c]     = acc[nt][0];
                    red[r0 * RED_STR + c + 1] = acc[nt][1];
                    red[r1 * RED_STR + c]     = acc[nt][2];
                    red[r1 * RED_STR + c + 1] = acc[nt][3];
                }
            }
            __syncthreads();
            if (kh == 0) {
#pragma unroll
                for (int nt = 0; nt < 4; ++nt) {
                    int c = nt * 8 + c0;
                    red[r0 * RED_STR + c]     += acc[nt][0];
                    red[r0 * RED_STR + c + 1] += acc[nt][1];
                    red[r1 * RED_STR + c]     += acc[nt][2];
                    red[r1 * RED_STR + c + 1] += acc[nt][3];
                }
            }
            __syncthreads();
        }

        // ---- epilogue: thread = (batch ep_b, h-pair ep_hp); cx in registers
        {
            float xb = xs[ep_b];
            float vout[2];
#pragma unroll
            for (int j = 0; j < 2; ++j) {
                int h = ep_hp * 2 + j;
                float pf = red[(0*32 + h) * RED_STR + ep_b] + fmaf(wxb_sm[0*32+h], xb, bias_sm[0*32+h]);
                float pi = red[(1*32 + h) * RED_STR + ep_b] + fmaf(wxb_sm[1*32+h], xb, bias_sm[1*32+h]);
                float pg = red[(2*32 + h) * RED_STR + ep_b] + fmaf(wxb_sm[2*32+h], xb, bias_sm[2*32+h]);
                float po = red[(3*32 + h) * RED_STR + ep_b] + fmaf(wxb_sm[3*32+h], xb, bias_sm[3*32+h]);
                float f  = fast_sigmoid(pf);
                float ii = fast_sigmoid(pi);
                float gg = fast_tanh(pg);
                float oo = fast_sigmoid(po);
                cx[j] = fmaf(f, cx[j], ii * gg);
                vout[j] = oo * fast_tanh(cx[j]);
            }
            // pack hi/lo bf16 pair and store into next image's packet slots
            float f0h = __bfloat162float(__float2bfloat16(vout[0]));
            float f1h = __bfloat162float(__float2bfloat16(vout[1]));
            uint32_t hw = pack2bf(f0h, f1h);
            uint32_t lw = pack2bf(vout[0] - f0h, vout[1] - f1h);

            int kglob = h0 + ep_hp * 2;          // global k (source hidden)
            int kc    = kglob >> 4;
            int j2    = (kglob & 15) >> 1;       // 0..7
            int c     = (j2 < 4) ? j2 : (j2 - 4);
            int slot  = (j2 < 4) ? 0 : 4;
            uint8_t* img = (uint8_t*)g_hximg4
                         + (size_t)((p ^ 1) * GROUPS + group) * IMG_BYTES;
            uint8_t* base = img + ep_b * ROW_BYTES + kc * 64 + c * 16 + slot;
            __stcg((unsigned int*)(base),     hw);
            __stcg((unsigned int*)(base + 8), lw);

            if (t == SEQ - 1) {
                *(float2*)(g_hxf32 + (group * GROUP_B + ep_b) * HID + kglob) =
                    make_float2(vout[0], vout[1]);
            }
        }
        CLUSTER_SYNC_();   // arrive = release: publishes the .cg stores
        p ^= 1;
    }

    // ---- head (rank-0 CTA per cluster): logits[b] = hx . w_head + b_head
    if (ctarank == 0 && tid < 256) {
        const int bb   = tid >> 3;   // 0..31
        const int part = tid & 7;    // 0..7
        const float* src = g_hxf32 + (group * GROUP_B + bb) * HID + part * 32;
        float s = 0.0f;
#pragma unroll
        for (int kk = 0; kk < 32; ++kk)
            s = fmaf(src[kk], __ldg(w_head + part * 32 + kk), s);
        s += __shfl_xor_sync(0xffffffffu, s, 4);
        s += __shfl_xor_sync(0xffffffffu, s, 2);
        s += __shfl_xor_sync(0xffffffffu, s, 1);
        if (part == 0) logits[b0 + bb] = s + __ldg(b_head);
    }
}

// ======================= launch ===========================================

extern "C" void kernel_launch(void* const* d_in, const int* in_sizes, int n_in,
                              void* d_out, int out_size)
{
    const float* x      = (const float*)d_in[0];
    const float* w1     = (const float*)d_in[1];
    const float* b1     = (const float*)d_in[2];
    const float* w2     = (const float*)d_in[3];
    const float* b2     = (const float*)d_in[4];
    const float* w3     = (const float*)d_in[5];
    const float* b3     = (const float*)d_in[6];
    const float* w4     = (const float*)d_in[7];
    const float* b4     = (const float*)d_in[8];
    const float* w5     = (const float*)d_in[9];
    const float* b5     = (const float*)d_in[10];
    const float* w6     = (const float*)d_in[11];
    const float* b6     = (const float*)d_in[12];
    const float* w7     = (const float*)d_in[13];
    const float* b7     = (const float*)d_in[14];
    const float* w_f    = (const float*)d_in[15];
    const float* b_f    = (const float*)d_in[16];
    const float* w_i    = (const float*)d_in[17];
    const float* b_i    = (const float*)d_in[18];
    const float* w_g    = (const float*)d_in[19];
    const float* b_g    = (const float*)d_in[20];
    const float* w_o    = (const float*)d_in[21];
    const float* b_o    = (const float*)d_in[22];
    const float* w_head = (const float*)d_in[23];
    const float* b_head = (const float*)d_in[24];

    float* out = (float*)d_out;

    cnn_kernel<<<(BATCH * SEQ) / 256, 256>>>(x, w1, b1, w2, b2, w3, b3, w4, b4,
                                             w5, b5, w6, b6, w7, b7, out);

    cudaFuncSetAttribute(lstm_kernel, cudaFuncAttributeMaxDynamicSharedMemorySize,
                         SMEM_BYTES);
    lstm_kernel<<<LSTM_CTAS, LSTM_THREADS, SMEM_BYTES>>>(
        out, w_f, b_f, w_i, b_i, w_g, b_g, w_o, b_o, w_head, b_head,
        out + BATCH * SEQ);
}